// round 2
// baseline (speedup 1.0000x reference)
#include <cuda_runtime.h>
#include <stdint.h>
#include <math.h>

// Problem constants (fixed problem instance; D must equal blockDim for the
// thread-owns-dimension layout).
#define DIM 256
#define NMAX 10016
#define NW_PAD 320            // ceil(10000/32)=313, padded row stride (words)
#define CN_CAP 256            // max common neighbors tracked (expected ~0.09, worst s==d ~deg)

// Scratch (static device globals — no runtime allocation allowed).
__device__ uint32_t g_bits[(size_t)NMAX * NW_PAD];   // ~12.8 MB bitmask adjacency
__device__ float    g_xn[(size_t)NMAX * DIM];        // ~10.3 MB normalized features

// ---------------------------------------------------------------------------
// Pass 1: one block per node row i.
//   - read adj[i,:] once (coalesced), ballot-pack to bitmask
//   - degree via popc
//   - y[i] = emb[i] + (sum_{c: adj[i,c]=1} emb[c]) / (deg + 1e-6)
//   - xn[i] = y[i] / max(||y[i]||, 1e-8)
// Thread t owns feature dimension t (DIM == 256 == blockDim.x).
// ---------------------------------------------------------------------------
__global__ __launch_bounds__(256) void cnp_pass1(
    const float* __restrict__ emb,
    const float* __restrict__ adj,
    int N, int NW)
{
    const int i    = blockIdx.x;
    const int tid  = threadIdx.x;
    const int lane = tid & 31;
    const int warp = tid >> 5;

    __shared__ uint32_t s_words[NW_PAD];
    __shared__ float    s_red[8];
    __shared__ float    s_red2[8];

    const float* __restrict__ row = adj + (size_t)i * N;

    // --- pack adjacency row into bitmask (8 warps stripe over words) ---
    for (int w = warp; w < NW; w += 8) {
        const int c = (w << 5) + lane;
        const float v = (c < N) ? __ldg(row + c) : 0.0f;
        const uint32_t m = __ballot_sync(0xffffffffu, v != 0.0f);
        if (lane == 0) s_words[w] = m;
    }
    __syncthreads();

    // --- write bitmask to global + degree count ---
    int cnt = 0;
    for (int w = tid; w < NW; w += 256) {
        const uint32_t m = s_words[w];
        g_bits[(size_t)i * NW_PAD + w] = m;
        cnt += __popc(m);
    }
    #pragma unroll
    for (int o = 16; o; o >>= 1) cnt += __shfl_xor_sync(0xffffffffu, cnt, o);
    if (lane == 0) s_red[warp] = (float)cnt;
    __syncthreads();
    float deg = 1e-6f;
    #pragma unroll
    for (int k = 0; k < 8; k++) deg += s_red[k];

    // --- sparse row of adj @ emb: iterate set bits, coalesced feature loads ---
    float acc = 0.0f;
    for (int w = 0; w < NW; ++w) {
        uint32_t m = s_words[w];
        while (m) {
            const int b = __ffs(m) - 1;
            m &= m - 1;
            const int c = (w << 5) + b;
            acc += __ldg(emb + (size_t)c * DIM + tid);
        }
    }

    const float xv = __ldg(emb + (size_t)i * DIM + tid) + acc / deg;

    // --- block-reduce squared norm ---
    float p = xv * xv;
    #pragma unroll
    for (int o = 16; o; o >>= 1) p += __shfl_xor_sync(0xffffffffu, p, o);
    if (lane == 0) s_red2[warp] = p;
    __syncthreads();
    float nrm2 = 0.0f;
    #pragma unroll
    for (int k = 0; k < 8; k++) nrm2 += s_red2[k];

    const float inv = 1.0f / fmaxf(sqrtf(nrm2), 1e-8f);
    g_xn[(size_t)i * DIM + tid] = xv * inv;
}

// ---------------------------------------------------------------------------
// Pass 2: one block per query edge q. Intersect bit-rows of (s, d), then for
// each common neighbor c accumulate cos(xn_s, xn_c) * cos(xn_d, xn_c).
// (xn already normalized -> cos == dot product.)
// ---------------------------------------------------------------------------
__global__ __launch_bounds__(256) void cnp_pass2(
    const int* __restrict__ edges,   // int32 [2, Q] (JAX canonicalizes int64->int32)
    float* __restrict__ out,
    int NW, int Q)
{
    const int q    = blockIdx.x;
    const int tid  = threadIdx.x;
    const int lane = tid & 31;
    const int warp = tid >> 5;

    __shared__ int   s_cnt;
    __shared__ int   s_list[CN_CAP];
    __shared__ float s_redL[8];
    __shared__ float s_redR[8];

    const int s = edges[q];
    const int d = edges[Q + q];

    if (tid == 0) s_cnt = 0;
    __syncthreads();

    const uint32_t* __restrict__ bs = g_bits + (size_t)s * NW_PAD;
    const uint32_t* __restrict__ bd = g_bits + (size_t)d * NW_PAD;
    for (int w = tid; w < NW; w += 256) {
        uint32_t m = __ldg(bs + w) & __ldg(bd + w);
        while (m) {
            const int b = __ffs(m) - 1;
            m &= m - 1;
            const int idx = atomicAdd(&s_cnt, 1);
            if (idx < CN_CAP) s_list[idx] = (w << 5) + b;
        }
    }
    __syncthreads();

    const int cn = min(s_cnt, CN_CAP);
    float acc = 0.0f;
    if (cn > 0) {
        const float xs = g_xn[(size_t)s * DIM + tid];
        const float xd = g_xn[(size_t)d * DIM + tid];
        for (int k = 0; k < cn; ++k) {
            const int c = s_list[k];
            const float xc = g_xn[(size_t)c * DIM + tid];
            float pl = xs * xc;
            float pr = xd * xc;
            #pragma unroll
            for (int o = 16; o; o >>= 1) {
                pl += __shfl_xor_sync(0xffffffffu, pl, o);
                pr += __shfl_xor_sync(0xffffffffu, pr, o);
            }
            if (lane == 0) { s_redL[warp] = pl; s_redR[warp] = pr; }
            __syncthreads();
            float L = 0.0f, R = 0.0f;
            #pragma unroll
            for (int j = 0; j < 8; j++) { L += s_redL[j]; R += s_redR[j]; }
            acc += L * R;
            __syncthreads();
        }
    }

    if (tid == 0) out[q] = 1.0f / (1.0f + expf(-acc));
}

// ---------------------------------------------------------------------------
// Launch — identify inputs by element count (robust to metadata ordering):
//   adj = N*N (~1e8), emb = N*DIM (2.56M), edges = 2*Q (8192)
// ---------------------------------------------------------------------------
extern "C" void kernel_launch(void* const* d_in, const int* in_sizes, int n_in,
                              void* d_out, int out_size)
{
    int i_adj = 0, i_emb = 0, i_edg = 0;
    long long best_adj = -1, best_emb = -1, best_edg = 0x7fffffffffffLL;
    for (int k = 0; k < n_in; ++k) {
        long long sz = in_sizes[k];
        if (sz > best_adj) { best_adj = sz; i_adj = k; }
        if (sz < best_edg) { best_edg = sz; i_edg = k; }
    }
    best_emb = -1;
    for (int k = 0; k < n_in; ++k) {
        if (k == i_adj || k == i_edg) continue;
        if (in_sizes[k] > best_emb) { best_emb = in_sizes[k]; i_emb = k; }
    }

    const float* emb   = (const float*)d_in[i_emb];   // [N, 256] fp32
    const float* adj   = (const float*)d_in[i_adj];   // [N, N]   fp32 0/1
    const int*   edges = (const int*)d_in[i_edg];     // [2, Q]   int32
    float*       out   = (float*)d_out;               // [Q]      fp32

    const int N  = in_sizes[i_emb] / DIM;  // 10000
    const int Q  = in_sizes[i_edg] / 2;    // 4096
    const int NW = (N + 31) / 32;          // 313

    cnp_pass1<<<N, 256>>>(emb, adj, N, NW);
    cnp_pass2<<<Q, 256>>>(edges, out, NW, Q);
}

// round 3
// speedup vs baseline: 2.6607x; 2.6607x over previous
#include <cuda_runtime.h>
#include <stdint.h>
#include <math.h>

#define DIM 256
#define NMAX 10016
#define NW_PAD 320            // padded row stride in words (divisible by 4 for uint4)
#define LIST_CAP 512          // max degree tracked (Binomial(1e4,0.003): mean 30, max ~60)
#define P2_WARPS 8
#define P2_CN_CAP 128

// Scratch (static device globals; zero-initialized — pad words stay zero forever).
__device__ uint32_t g_bits[(size_t)NMAX * NW_PAD];   // ~12.8 MB bitmask adjacency
__device__ float    g_xn[(size_t)NMAX * DIM];        // ~10.3 MB normalized features

// ---------------------------------------------------------------------------
// Pass 1: one block (256 threads) per node row i.
// Each THREAD packs whole 32-bit words from 8 unrolled float4 loads (MLP=8),
// builds the neighbor index list in smem, then thread t (owning feature dim t)
// gathers emb rows with 4 independent partial sums.
// ---------------------------------------------------------------------------
__global__ __launch_bounds__(256) void cnp_pass1(
    const float* __restrict__ emb,
    const float* __restrict__ adj,
    int N, int NW)
{
    const int i    = blockIdx.x;
    const int tid  = threadIdx.x;
    const int lane = tid & 31;
    const int warp = tid >> 5;

    __shared__ int   s_cnt;
    __shared__ int   s_deg;
    __shared__ int   s_list[LIST_CAP];
    __shared__ float s_red[8];

    if (tid == 0) { s_cnt = 0; s_deg = 0; }
    __syncthreads();

    const float* __restrict__ row = adj + (size_t)i * N;

    // --- pack: thread handles words tid, tid+256 ---
    for (int w = tid; w < NW; w += 256) {
        uint32_t bits = 0;
        if (w < NW - 1) {
            #pragma unroll
            for (int j = 0; j < 8; j++) {
                const float4 v = __ldcs((const float4*)(row + (w << 5) + (j << 2)));
                bits |= (uint32_t)(v.x != 0.0f) << (4*j + 0);
                bits |= (uint32_t)(v.y != 0.0f) << (4*j + 1);
                bits |= (uint32_t)(v.z != 0.0f) << (4*j + 2);
                bits |= (uint32_t)(v.w != 0.0f) << (4*j + 3);
            }
        } else {
            // tail word: guard columns >= N
            for (int b = 0; b < 32; b++) {
                const int c = (w << 5) + b;
                if (c < N && __ldcs(row + c) != 0.0f) bits |= 1u << b;
            }
        }
        g_bits[(size_t)i * NW_PAD + w] = bits;
        if (bits) {
            atomicAdd(&s_deg, __popc(bits));
            uint32_t m = bits;
            while (m) {
                const int b = __ffs(m) - 1;
                m &= m - 1;
                const int idx = atomicAdd(&s_cnt, 1);
                if (idx < LIST_CAP) s_list[idx] = (w << 5) + b;
            }
        }
    }
    __syncthreads();

    const float deg = (float)s_deg + 1e-6f;
    const int   cn  = min(s_cnt, LIST_CAP);

    // --- gather: 4 independent partial sums (MLP=4 on L2-resident emb) ---
    float a0 = 0.f, a1 = 0.f, a2 = 0.f, a3 = 0.f;
    int k = 0;
    for (; k + 4 <= cn; k += 4) {
        a0 += emb[(size_t)s_list[k+0] * DIM + tid];
        a1 += emb[(size_t)s_list[k+1] * DIM + tid];
        a2 += emb[(size_t)s_list[k+2] * DIM + tid];
        a3 += emb[(size_t)s_list[k+3] * DIM + tid];
    }
    for (; k < cn; k++) a0 += emb[(size_t)s_list[k] * DIM + tid];

    const float xv = emb[(size_t)i * DIM + tid] + (a0 + a1 + a2 + a3) / deg;

    // --- block-reduce squared norm ---
    float p = xv * xv;
    #pragma unroll
    for (int o = 16; o; o >>= 1) p += __shfl_xor_sync(0xffffffffu, p, o);
    if (lane == 0) s_red[warp] = p;
    __syncthreads();
    float nrm2 = 0.0f;
    #pragma unroll
    for (int j = 0; j < 8; j++) nrm2 += s_red[j];

    const float inv = 1.0f / fmaxf(sqrtf(nrm2), 1e-8f);
    g_xn[(size_t)i * DIM + tid] = xv * inv;
}

// ---------------------------------------------------------------------------
// Pass 2: one WARP per query. uint4 intersection over the padded 320-word
// bit-rows (pads are zero), then per-common-neighbor warp dot products.
// xn is pre-normalized, so cos == dot.
// ---------------------------------------------------------------------------
__global__ __launch_bounds__(P2_WARPS * 32) void cnp_pass2(
    const int* __restrict__ edges,   // int32 [2, Q]
    float* __restrict__ out,
    int Q)
{
    const int warp = threadIdx.x >> 5;
    const int lane = threadIdx.x & 31;
    const int q    = blockIdx.x * P2_WARPS + warp;

    __shared__ int s_list[P2_WARPS][P2_CN_CAP];
    __shared__ int s_cnt[P2_WARPS];

    if (q >= Q) return;
    if (lane == 0) s_cnt[warp] = 0;
    __syncwarp();

    const int s = edges[q];
    const int d = edges[Q + q];

    const uint4* __restrict__ bs = (const uint4*)(g_bits + (size_t)s * NW_PAD);
    const uint4* __restrict__ bd = (const uint4*)(g_bits + (size_t)d * NW_PAD);

    for (int ci = lane; ci < NW_PAD / 4; ci += 32) {
        const uint4 a = bs[ci];
        const uint4 b = bd[ci];
        uint32_t m[4] = { a.x & b.x, a.y & b.y, a.z & b.z, a.w & b.w };
        #pragma unroll
        for (int wd = 0; wd < 4; wd++) {
            uint32_t m2 = m[wd];
            while (m2) {
                const int bit = __ffs(m2) - 1;
                m2 &= m2 - 1;
                const int idx = atomicAdd(&s_cnt[warp], 1);
                if (idx < P2_CN_CAP) s_list[warp][idx] = (ci << 7) + (wd << 5) + bit;
            }
        }
    }
    __syncwarp();

    const int cn = min(s_cnt[warp], P2_CN_CAP);
    float acc = 0.0f;
    if (cn > 0) {
        float xs[8], xd[8];
        #pragma unroll
        for (int j = 0; j < 8; j++) {
            xs[j] = g_xn[(size_t)s * DIM + lane + 32*j];
            xd[j] = g_xn[(size_t)d * DIM + lane + 32*j];
        }
        for (int k = 0; k < cn; k++) {
            const int c = s_list[warp][k];
            float pl = 0.f, pr = 0.f;
            #pragma unroll
            for (int j = 0; j < 8; j++) {
                const float xc = g_xn[(size_t)c * DIM + lane + 32*j];
                pl += xs[j] * xc;
                pr += xd[j] * xc;
            }
            #pragma unroll
            for (int o = 16; o; o >>= 1) {
                pl += __shfl_xor_sync(0xffffffffu, pl, o);
                pr += __shfl_xor_sync(0xffffffffu, pr, o);
            }
            acc += pl * pr;
        }
    }

    if (lane == 0) out[q] = 1.0f / (1.0f + expf(-acc));
}

// ---------------------------------------------------------------------------
// Launch — identify inputs by element count (robust to metadata ordering):
//   adj = N*N (~1e8), emb = N*DIM (2.56M), edges = 2*Q (8192)
// ---------------------------------------------------------------------------
extern "C" void kernel_launch(void* const* d_in, const int* in_sizes, int n_in,
                              void* d_out, int out_size)
{
    int i_adj = 0, i_edg = 0;
    long long best_adj = -1, best_edg = 0x7fffffffffffLL;
    for (int k = 0; k < n_in; ++k) {
        long long sz = in_sizes[k];
        if (sz > best_adj) { best_adj = sz; i_adj = k; }
        if (sz < best_edg) { best_edg = sz; i_edg = k; }
    }
    int i_emb = 0; long long best_emb = -1;
    for (int k = 0; k < n_in; ++k) {
        if (k == i_adj || k == i_edg) continue;
        if (in_sizes[k] > best_emb) { best_emb = in_sizes[k]; i_emb = k; }
    }

    const float* emb   = (const float*)d_in[i_emb];   // [N, 256] fp32
    const float* adj   = (const float*)d_in[i_adj];   // [N, N]   fp32 0/1
    const int*   edges = (const int*)d_in[i_edg];     // [2, Q]   int32
    float*       out   = (float*)d_out;               // [Q]      fp32

    const int N  = in_sizes[i_emb] / DIM;  // 10000
    const int Q  = in_sizes[i_edg] / 2;    // 4096
    const int NW = (N + 31) / 32;          // 313

    cnp_pass1<<<N, 256>>>(emb, adj, N, NW);
    cnp_pass2<<<(Q + P2_WARPS - 1) / P2_WARPS, P2_WARPS * 32>>>(edges, out, Q);
}

// round 4
// speedup vs baseline: 3.3047x; 1.2420x over previous
#include <cuda_runtime.h>
#include <stdint.h>
#include <math.h>

#define DIM 256
#define NMAX 10016
#define NW_PAD 320            // padded row stride in words (divisible by 4 for uint4)
#define LIST_CAP 512
#define P2_WARPS 8
#define P2_CN_CAP 128

// Interleaved bit layout (internal format, both passes agree):
//   word W, bit b  <->  column ((W>>2)<<7) + (b<<2) + (W&3)

// Scratch (static device globals; zero-initialized).
__device__ uint32_t g_bits[(size_t)NMAX * NW_PAD];   // ~12.8 MB bitmask adjacency
__device__ float    g_xn[(size_t)NMAX * DIM];        // ~10.3 MB normalized features

// ---------------------------------------------------------------------------
// Pass 1: one block (256 threads = 8 warps) per node row i.
// Pack: warp processes 512B groups COALESCED (lane L -> col g*128+4L),
// 4 groups in flight per warp (MLP), bits assembled via 4 ballots/group.
// Then: neighbor list from bit scan, gather emb (thread owns feature dim),
// normalize, store xn.
// ---------------------------------------------------------------------------
__global__ __launch_bounds__(256) void cnp_pass1(
    const float* __restrict__ emb,
    const float* __restrict__ adj,
    int N)
{
    const int i    = blockIdx.x;
    const int tid  = threadIdx.x;
    const int lane = tid & 31;
    const int warp = tid >> 5;

    __shared__ uint32_t s_words[NW_PAD];
    __shared__ int   s_cnt;
    __shared__ int   s_deg;
    __shared__ int   s_list[LIST_CAP];
    __shared__ float s_red[8];

    if (tid == 0) { s_cnt = 0; s_deg = 0; }
    for (int w = tid; w < NW_PAD; w += 256) s_words[w] = 0;
    __syncthreads();

    const float* __restrict__ row = adj + (size_t)i * N;
    const int NG = (N + 127) >> 7;          // 512B groups per row (79 for N=10000)

    // --- coalesced pack: warp w handles groups g ≡ w (mod 8), 4 in flight ---
    for (int g0 = warp; g0 < NG; g0 += 32) {
        float4 v[4];
        #pragma unroll
        for (int u = 0; u < 4; u++) {
            const int g = g0 + (u << 3);
            v[u] = make_float4(0.f, 0.f, 0.f, 0.f);
            if (g < NG) {
                const int col = (g << 7) + (lane << 2);
                if (col + 4 <= N) {
                    v[u] = __ldcs((const float4*)(row + col));
                } else if (col < N) {
                    float t0 = __ldcs(row + col);
                    float t1 = (col + 1 < N) ? __ldcs(row + col + 1) : 0.f;
                    float t2 = (col + 2 < N) ? __ldcs(row + col + 2) : 0.f;
                    v[u] = make_float4(t0, t1, t2, 0.f);
                }
            }
        }
        #pragma unroll
        for (int u = 0; u < 4; u++) {
            const int g = g0 + (u << 3);
            if (g < NG) {   // warp-uniform predicate
                const uint32_t b0 = __ballot_sync(0xffffffffu, v[u].x != 0.f);
                const uint32_t b1 = __ballot_sync(0xffffffffu, v[u].y != 0.f);
                const uint32_t b2 = __ballot_sync(0xffffffffu, v[u].z != 0.f);
                const uint32_t b3 = __ballot_sync(0xffffffffu, v[u].w != 0.f);
                if (lane == 0) {
                    s_words[(g << 2) + 0] = b0;
                    s_words[(g << 2) + 1] = b1;
                    s_words[(g << 2) + 2] = b2;
                    s_words[(g << 2) + 3] = b3;
                }
            }
        }
    }
    __syncthreads();

    // --- write bitmask (vectorized), degree, neighbor list ---
    {
        uint4* dst = (uint4*)(g_bits + (size_t)i * NW_PAD);
        const uint4* src = (const uint4*)s_words;
        for (int c = tid; c < NW_PAD / 4; c += 256) dst[c] = src[c];
    }
    for (int w = tid; w < NW_PAD; w += 256) {
        uint32_t m = s_words[w];
        if (m) {
            atomicAdd(&s_deg, __popc(m));
            const int base = ((w >> 2) << 7) + (w & 3);
            while (m) {
                const int b = __ffs(m) - 1;
                m &= m - 1;
                const int idx = atomicAdd(&s_cnt, 1);
                if (idx < LIST_CAP) s_list[idx] = base + (b << 2);
            }
        }
    }
    __syncthreads();

    const float deg = (float)s_deg + 1e-6f;
    const int   cn  = min(s_cnt, LIST_CAP);

    // --- gather: 4 independent partial sums (MLP=4, emb mostly L2-resident) ---
    float a0 = 0.f, a1 = 0.f, a2 = 0.f, a3 = 0.f;
    int k = 0;
    for (; k + 4 <= cn; k += 4) {
        a0 += emb[(size_t)s_list[k+0] * DIM + tid];
        a1 += emb[(size_t)s_list[k+1] * DIM + tid];
        a2 += emb[(size_t)s_list[k+2] * DIM + tid];
        a3 += emb[(size_t)s_list[k+3] * DIM + tid];
    }
    for (; k < cn; k++) a0 += emb[(size_t)s_list[k] * DIM + tid];

    const float xv = emb[(size_t)i * DIM + tid] + (a0 + a1 + a2 + a3) / deg;

    // --- block-reduce squared norm, normalize, store ---
    float p = xv * xv;
    #pragma unroll
    for (int o = 16; o; o >>= 1) p += __shfl_xor_sync(0xffffffffu, p, o);
    if (lane == 0) s_red[warp] = p;
    __syncthreads();
    float nrm2 = 0.0f;
    #pragma unroll
    for (int j = 0; j < 8; j++) nrm2 += s_red[j];

    const float inv = 1.0f / fmaxf(sqrtf(nrm2), 1e-8f);
    g_xn[(size_t)i * DIM + tid] = xv * inv;
}

// ---------------------------------------------------------------------------
// Pass 2: one WARP per query. uint4 AND over the padded bit-rows, decode via
// the interleaved layout, then warp dot products (xn normalized -> cos==dot).
// ---------------------------------------------------------------------------
__global__ __launch_bounds__(P2_WARPS * 32) void cnp_pass2(
    const int* __restrict__ edges,   // int32 [2, Q]
    float* __restrict__ out,
    int Q)
{
    const int warp = threadIdx.x >> 5;
    const int lane = threadIdx.x & 31;
    const int q    = blockIdx.x * P2_WARPS + warp;

    __shared__ int s_list[P2_WARPS][P2_CN_CAP];
    __shared__ int s_cnt[P2_WARPS];

    if (q >= Q) return;
    if (lane == 0) s_cnt[warp] = 0;
    __syncwarp();

    const int s = edges[q];
    const int d = edges[Q + q];

    const uint4* __restrict__ bs = (const uint4*)(g_bits + (size_t)s * NW_PAD);
    const uint4* __restrict__ bd = (const uint4*)(g_bits + (size_t)d * NW_PAD);

    for (int ci = lane; ci < NW_PAD / 4; ci += 32) {
        const uint4 a = bs[ci];
        const uint4 b = bd[ci];
        uint32_t m[4] = { a.x & b.x, a.y & b.y, a.z & b.z, a.w & b.w };
        #pragma unroll
        for (int wd = 0; wd < 4; wd++) {
            uint32_t m2 = m[wd];
            const int W = (ci << 2) + wd;
            const int base = ((W >> 2) << 7) + (W & 3);
            while (m2) {
                const int bit = __ffs(m2) - 1;
                m2 &= m2 - 1;
                const int idx = atomicAdd(&s_cnt[warp], 1);
                if (idx < P2_CN_CAP) s_list[warp][idx] = base + (bit << 2);
            }
        }
    }
    __syncwarp();

    const int cn = min(s_cnt[warp], P2_CN_CAP);
    float acc = 0.0f;
    if (cn > 0) {
        float xs[8], xd[8];
        #pragma unroll
        for (int j = 0; j < 8; j++) {
            xs[j] = g_xn[(size_t)s * DIM + lane + 32*j];
            xd[j] = g_xn[(size_t)d * DIM + lane + 32*j];
        }
        for (int k = 0; k < cn; k++) {
            const int c = s_list[warp][k];
            float pl = 0.f, pr = 0.f;
            #pragma unroll
            for (int j = 0; j < 8; j++) {
                const float xc = g_xn[(size_t)c * DIM + lane + 32*j];
                pl += xs[j] * xc;
                pr += xd[j] * xc;
            }
            #pragma unroll
            for (int o = 16; o; o >>= 1) {
                pl += __shfl_xor_sync(0xffffffffu, pl, o);
                pr += __shfl_xor_sync(0xffffffffu, pr, o);
            }
            acc += pl * pr;
        }
    }

    if (lane == 0) out[q] = 1.0f / (1.0f + expf(-acc));
}

// ---------------------------------------------------------------------------
// Launch — identify inputs by element count (robust to metadata ordering).
// ---------------------------------------------------------------------------
extern "C" void kernel_launch(void* const* d_in, const int* in_sizes, int n_in,
                              void* d_out, int out_size)
{
    int i_adj = 0, i_edg = 0;
    long long best_adj = -1, best_edg = 0x7fffffffffffLL;
    for (int k = 0; k < n_in; ++k) {
        long long sz = in_sizes[k];
        if (sz > best_adj) { best_adj = sz; i_adj = k; }
        if (sz < best_edg) { best_edg = sz; i_edg = k; }
    }
    int i_emb = 0; long long best_emb = -1;
    for (int k = 0; k < n_in; ++k) {
        if (k == i_adj || k == i_edg) continue;
        if (in_sizes[k] > best_emb) { best_emb = in_sizes[k]; i_emb = k; }
    }

    const float* emb   = (const float*)d_in[i_emb];   // [N, 256] fp32
    const float* adj   = (const float*)d_in[i_adj];   // [N, N]   fp32 0/1
    const int*   edges = (const int*)d_in[i_edg];     // [2, Q]   int32
    float*       out   = (float*)d_out;               // [Q]      fp32

    const int N = in_sizes[i_emb] / DIM;  // 10000
    const int Q = in_sizes[i_edg] / 2;    // 4096

    cnp_pass1<<<N, 256>>>(emb, adj, N);
    cnp_pass2<<<(Q + P2_WARPS - 1) / P2_WARPS, P2_WARPS * 32>>>(edges, out, Q);
}

// round 5
// speedup vs baseline: 3.3116x; 1.0021x over previous
#include <cuda_runtime.h>
#include <cuda_fp16.h>
#include <stdint.h>
#include <math.h>

#define DIM 256
#define NMAX 10016
#define NW_PAD 320            // padded row stride in words (divisible by 4 for uint4)
#define LIST_CAP 512
#define P2_WARPS 8
#define P2_CN_CAP 128

// Interleaved bit layout (internal format, both passes agree):
//   word W, bit b  <->  column ((W>>2)<<7) + (b<<2) + (W&3)

// Scratch (static device globals; zero-initialized).
__device__ uint32_t g_bits[(size_t)NMAX * NW_PAD];   // ~12.8 MB bitmask adjacency
__device__ float    g_xn[(size_t)NMAX * DIM];        // ~10.3 MB normalized features
__device__ __half   g_emb16[(size_t)NMAX * DIM];     // ~5.1 MB fp16 emb copy (gather source)

// ---------------------------------------------------------------------------
// Pass 0: fp32 emb -> fp16 copy (gather halves LTS traffic in pass1).
// ---------------------------------------------------------------------------
__global__ __launch_bounds__(256) void cnp_convert(
    const float* __restrict__ emb, int total4)
{
    const int t = blockIdx.x * blockDim.x + threadIdx.x;
    if (t < total4) {
        const float4 f = __ldg((const float4*)emb + t);
        __half2 ha = __floats2half2_rn(f.x, f.y);
        __half2 hb = __floats2half2_rn(f.z, f.w);
        uint2 u;
        u.x = *(const uint32_t*)&ha;
        u.y = *(const uint32_t*)&hb;
        ((uint2*)g_emb16)[t] = u;
    }
}

// ---------------------------------------------------------------------------
// Pass 1: one block (256 threads = 8 warps) per node row i.
// Coalesced pack (warp covers 512B/group, 4 groups in flight), ballot-assemble
// bits; neighbor list; fp16 gather; normalize; store fp32 xn.
// ---------------------------------------------------------------------------
__global__ __launch_bounds__(256) void cnp_pass1(
    const float* __restrict__ emb,
    const float* __restrict__ adj,
    int N)
{
    const int i    = blockIdx.x;
    const int tid  = threadIdx.x;
    const int lane = tid & 31;
    const int warp = tid >> 5;

    __shared__ uint32_t s_words[NW_PAD];
    __shared__ int   s_cnt;
    __shared__ int   s_deg;
    __shared__ int   s_list[LIST_CAP];
    __shared__ float s_red[8];

    if (tid == 0) { s_cnt = 0; s_deg = 0; }
    for (int w = tid; w < NW_PAD; w += 256) s_words[w] = 0;
    __syncthreads();

    const float* __restrict__ row = adj + (size_t)i * N;
    const int NG = (N + 127) >> 7;          // 512B groups per row

    // --- coalesced pack: warp w handles groups g ≡ w (mod 8), 4 in flight ---
    for (int g0 = warp; g0 < NG; g0 += 32) {
        float4 v[4];
        #pragma unroll
        for (int u = 0; u < 4; u++) {
            const int g = g0 + (u << 3);
            v[u] = make_float4(0.f, 0.f, 0.f, 0.f);
            if (g < NG) {
                const int col = (g << 7) + (lane << 2);
                if (col + 4 <= N) {
                    v[u] = __ldcs((const float4*)(row + col));
                } else if (col < N) {
                    float t0 = __ldcs(row + col);
                    float t1 = (col + 1 < N) ? __ldcs(row + col + 1) : 0.f;
                    float t2 = (col + 2 < N) ? __ldcs(row + col + 2) : 0.f;
                    v[u] = make_float4(t0, t1, t2, 0.f);
                }
            }
        }
        #pragma unroll
        for (int u = 0; u < 4; u++) {
            const int g = g0 + (u << 3);
            if (g < NG) {   // warp-uniform predicate
                const uint32_t b0 = __ballot_sync(0xffffffffu, v[u].x != 0.f);
                const uint32_t b1 = __ballot_sync(0xffffffffu, v[u].y != 0.f);
                const uint32_t b2 = __ballot_sync(0xffffffffu, v[u].z != 0.f);
                const uint32_t b3 = __ballot_sync(0xffffffffu, v[u].w != 0.f);
                if (lane == 0) {
                    s_words[(g << 2) + 0] = b0;
                    s_words[(g << 2) + 1] = b1;
                    s_words[(g << 2) + 2] = b2;
                    s_words[(g << 2) + 3] = b3;
                }
            }
        }
    }
    __syncthreads();

    // --- write bitmask (vectorized), degree, neighbor list ---
    {
        uint4* dst = (uint4*)(g_bits + (size_t)i * NW_PAD);
        const uint4* src = (const uint4*)s_words;
        for (int c = tid; c < NW_PAD / 4; c += 256) dst[c] = src[c];
    }
    for (int w = tid; w < NW_PAD; w += 256) {
        uint32_t m = s_words[w];
        if (m) {
            atomicAdd(&s_deg, __popc(m));
            const int base = ((w >> 2) << 7) + (w & 3);
            while (m) {
                const int b = __ffs(m) - 1;
                m &= m - 1;
                const int idx = atomicAdd(&s_cnt, 1);
                if (idx < LIST_CAP) s_list[idx] = base + (b << 2);
            }
        }
    }
    __syncthreads();

    const float deg = (float)s_deg + 1e-6f;
    const int   cn  = min(s_cnt, LIST_CAP);

    // --- gather from fp16 emb copy: 4 independent partial sums ---
    float a0 = 0.f, a1 = 0.f, a2 = 0.f, a3 = 0.f;
    int k = 0;
    for (; k + 4 <= cn; k += 4) {
        a0 += __half2float(__ldg(g_emb16 + (size_t)s_list[k+0] * DIM + tid));
        a1 += __half2float(__ldg(g_emb16 + (size_t)s_list[k+1] * DIM + tid));
        a2 += __half2float(__ldg(g_emb16 + (size_t)s_list[k+2] * DIM + tid));
        a3 += __half2float(__ldg(g_emb16 + (size_t)s_list[k+3] * DIM + tid));
    }
    for (; k < cn; k++)
        a0 += __half2float(__ldg(g_emb16 + (size_t)s_list[k] * DIM + tid));

    const float xv = emb[(size_t)i * DIM + tid] + (a0 + a1 + a2 + a3) / deg;

    // --- block-reduce squared norm, normalize, store ---
    float p = xv * xv;
    #pragma unroll
    for (int o = 16; o; o >>= 1) p += __shfl_xor_sync(0xffffffffu, p, o);
    if (lane == 0) s_red[warp] = p;
    __syncthreads();
    float nrm2 = 0.0f;
    #pragma unroll
    for (int j = 0; j < 8; j++) nrm2 += s_red[j];

    const float inv = 1.0f / fmaxf(sqrtf(nrm2), 1e-8f);
    g_xn[(size_t)i * DIM + tid] = xv * inv;
}

// ---------------------------------------------------------------------------
// Pass 2: one WARP per query. uint4 AND over the padded bit-rows, decode via
// the interleaved layout, then warp dot products (xn normalized -> cos==dot).
// ---------------------------------------------------------------------------
__global__ __launch_bounds__(P2_WARPS * 32) void cnp_pass2(
    const int* __restrict__ edges,   // int32 [2, Q]
    float* __restrict__ out,
    int Q)
{
    const int warp = threadIdx.x >> 5;
    const int lane = threadIdx.x & 31;
    const int q    = blockIdx.x * P2_WARPS + warp;

    __shared__ int s_list[P2_WARPS][P2_CN_CAP];
    __shared__ int s_cnt[P2_WARPS];

    if (q >= Q) return;
    if (lane == 0) s_cnt[warp] = 0;
    __syncwarp();

    const int s = edges[q];
    const int d = edges[Q + q];

    const uint4* __restrict__ bs = (const uint4*)(g_bits + (size_t)s * NW_PAD);
    const uint4* __restrict__ bd = (const uint4*)(g_bits + (size_t)d * NW_PAD);

    for (int ci = lane; ci < NW_PAD / 4; ci += 32) {
        const uint4 a = bs[ci];
        const uint4 b = bd[ci];
        uint32_t m[4] = { a.x & b.x, a.y & b.y, a.z & b.z, a.w & b.w };
        #pragma unroll
        for (int wd = 0; wd < 4; wd++) {
            uint32_t m2 = m[wd];
            const int W = (ci << 2) + wd;
            const int base = ((W >> 2) << 7) + (W & 3);
            while (m2) {
                const int bit = __ffs(m2) - 1;
                m2 &= m2 - 1;
                const int idx = atomicAdd(&s_cnt[warp], 1);
                if (idx < P2_CN_CAP) s_list[warp][idx] = base + (bit << 2);
            }
        }
    }
    __syncwarp();

    const int cn = min(s_cnt[warp], P2_CN_CAP);
    float acc = 0.0f;
    if (cn > 0) {
        float xs[8], xd[8];
        #pragma unroll
        for (int j = 0; j < 8; j++) {
            xs[j] = g_xn[(size_t)s * DIM + lane + 32*j];
            xd[j] = g_xn[(size_t)d * DIM + lane + 32*j];
        }
        for (int k = 0; k < cn; k++) {
            const int c = s_list[warp][k];
            float pl = 0.f, pr = 0.f;
            #pragma unroll
            for (int j = 0; j < 8; j++) {
                const float xc = g_xn[(size_t)c * DIM + lane + 32*j];
                pl += xs[j] * xc;
                pr += xd[j] * xc;
            }
            #pragma unroll
            for (int o = 16; o; o >>= 1) {
                pl += __shfl_xor_sync(0xffffffffu, pl, o);
                pr += __shfl_xor_sync(0xffffffffu, pr, o);
            }
            acc += pl * pr;
        }
    }

    if (lane == 0) out[q] = 1.0f / (1.0f + expf(-acc));
}

// ---------------------------------------------------------------------------
// Launch — identify inputs by element count (robust to metadata ordering).
// ---------------------------------------------------------------------------
extern "C" void kernel_launch(void* const* d_in, const int* in_sizes, int n_in,
                              void* d_out, int out_size)
{
    int i_adj = 0, i_edg = 0;
    long long best_adj = -1, best_edg = 0x7fffffffffffLL;
    for (int k = 0; k < n_in; ++k) {
        long long sz = in_sizes[k];
        if (sz > best_adj) { best_adj = sz; i_adj = k; }
        if (sz < best_edg) { best_edg = sz; i_edg = k; }
    }
    int i_emb = 0; long long best_emb = -1;
    for (int k = 0; k < n_in; ++k) {
        if (k == i_adj || k == i_edg) continue;
        if (in_sizes[k] > best_emb) { best_emb = in_sizes[k]; i_emb = k; }
    }

    const float* emb   = (const float*)d_in[i_emb];   // [N, 256] fp32
    const float* adj   = (const float*)d_in[i_adj];   // [N, N]   fp32 0/1
    const int*   edges = (const int*)d_in[i_edg];     // [2, Q]   int32
    float*       out   = (float*)d_out;               // [Q]      fp32

    const int N = in_sizes[i_emb] / DIM;  // 10000
    const int Q = in_sizes[i_edg] / 2;    // 4096

    const int total4 = (N * DIM) / 4;
    cnp_convert<<<(total4 + 255) / 256, 256>>>(emb, total4);
    cnp_pass1<<<N, 256>>>(emb, adj, N);
    cnp_pass2<<<(Q + P2_WARPS - 1) / P2_WARPS, P2_WARPS * 32>>>(edges, out, Q);
}

// round 6
// speedup vs baseline: 3.3416x; 1.0091x over previous
#include <cuda_runtime.h>
#include <stdint.h>
#include <math.h>

#define DIM 256
#define NMAX 10016
#define NW_PAD 320            // 80 groups * 4 words; divisible by 4 for uint4
#define NGRP 80               // padded 512B-groups per row (80*128 = 10240 cols)
#define GPW 10                // groups per warp (8 warps * 10 = 80)
#define LIST_CAP 512
#define GRID1 592             // 148 SMs * 4 blocks
#define P2_WARPS 8
#define P2_CN_CAP 128

// Interleaved bit layout (both passes agree):
//   word W, bit b  <->  column ((W>>2)<<7) + (b<<2) + (W&3)

// Scratch (static device globals; zero-initialized).
__device__ uint32_t g_bits[(size_t)NMAX * NW_PAD];   // ~12.8 MB bitmask adjacency
__device__ float    g_xn[(size_t)NMAX * DIM];        // ~10.3 MB normalized features

// ---------------------------------------------------------------------------
// Pass 1: persistent blocks, grid-stride over rows, software-pipelined:
// next row's adjacency loads are issued right after this row's ballots, so
// DRAM streaming never pauses during list-build / gather / normalize.
// Thread t owns feature dim t. Warp w owns groups [w*GPW, w*GPW+GPW).
// ---------------------------------------------------------------------------
__global__ __launch_bounds__(256) void cnp_pass1(
    const float* __restrict__ emb,
    const float* __restrict__ adj,
    int N)
{
    const int tid  = threadIdx.x;
    const int lane = tid & 31;
    const int warp = tid >> 5;

    __shared__ uint32_t s_words[NW_PAD];
    __shared__ int   s_cnt;
    __shared__ int   s_deg;
    __shared__ int   s_list[LIST_CAP];
    __shared__ float s_red[8];

    if (tid == 0) { s_cnt = 0; s_deg = 0; }
    __syncthreads();

    float4 v[GPW];

    // --- prologue: issue loads for first row ---
    {
        const int i0 = blockIdx.x;
        const float* __restrict__ row = adj + (size_t)i0 * N;
        #pragma unroll
        for (int u = 0; u < GPW; u++) {
            const int col = ((warp * GPW + u) << 7) + (lane << 2);
            v[u] = (i0 < N && col + 4 <= N) ? __ldcs((const float4*)(row + col))
                                            : make_float4(0.f, 0.f, 0.f, 0.f);
        }
    }

    for (int i = blockIdx.x; i < N; i += GRID1) {
        // --- ballots: consume v, produce this row's bit words ---
        #pragma unroll
        for (int u = 0; u < GPW; u++) {
            const int g = warp * GPW + u;
            const uint32_t b0 = __ballot_sync(0xffffffffu, v[u].x != 0.f);
            const uint32_t b1 = __ballot_sync(0xffffffffu, v[u].y != 0.f);
            const uint32_t b2 = __ballot_sync(0xffffffffu, v[u].z != 0.f);
            const uint32_t b3 = __ballot_sync(0xffffffffu, v[u].w != 0.f);
            if (lane == 0) {
                s_words[(g << 2) + 0] = b0;
                s_words[(g << 2) + 1] = b1;
                s_words[(g << 2) + 2] = b2;
                s_words[(g << 2) + 3] = b3;
            }
        }

        // --- prefetch: issue next row's loads NOW (resolve during gather) ---
        {
            const int inext = i + GRID1;
            const float* __restrict__ rown = adj + (size_t)inext * N;
            #pragma unroll
            for (int u = 0; u < GPW; u++) {
                const int col = ((warp * GPW + u) << 7) + (lane << 2);
                v[u] = (inext < N && col + 4 <= N)
                         ? __ldcs((const float4*)(rown + col))
                         : make_float4(0.f, 0.f, 0.f, 0.f);
            }
        }

        __syncthreads();   // A: s_words complete (also orders s_cnt/s_deg reset)

        // --- write bitmask + degree + neighbor list ---
        {
            uint4* dst = (uint4*)(g_bits + (size_t)i * NW_PAD);
            const uint4* src = (const uint4*)s_words;
            for (int c = tid; c < NW_PAD / 4; c += 256) dst[c] = src[c];
        }
        for (int w = tid; w < NW_PAD; w += 256) {
            uint32_t m = s_words[w];
            if (m) {
                atomicAdd(&s_deg, __popc(m));
                const int base = ((w >> 2) << 7) + (w & 3);
                while (m) {
                    const int b = __ffs(m) - 1;
                    m &= m - 1;
                    const int idx = atomicAdd(&s_cnt, 1);
                    if (idx < LIST_CAP) s_list[idx] = base + (b << 2);
                }
            }
        }
        __syncthreads();   // B: list/deg final

        const float deg = (float)s_deg + 1e-6f;
        const int   cn  = min(s_cnt, LIST_CAP);

        // --- gather: 8 independent partial sums (latency phase shortened) ---
        float a[8];
        #pragma unroll
        for (int j = 0; j < 8; j++) a[j] = 0.f;
        int k = 0;
        for (; k + 8 <= cn; k += 8) {
            #pragma unroll
            for (int j = 0; j < 8; j++)
                a[j] += emb[(size_t)s_list[k + j] * DIM + tid];
        }
        for (; k < cn; k++) a[0] += emb[(size_t)s_list[k] * DIM + tid];
        float asum = 0.f;
        #pragma unroll
        for (int j = 0; j < 8; j++) asum += a[j];

        const float xv = emb[(size_t)i * DIM + tid] + asum / deg;

        // --- block-reduce squared norm, normalize, store ---
        float p = xv * xv;
        #pragma unroll
        for (int o = 16; o; o >>= 1) p += __shfl_xor_sync(0xffffffffu, p, o);
        if (lane == 0) s_red[warp] = p;
        __syncthreads();   // C: also guards s_list/s_deg reuse next iteration
        float nrm2 = 0.0f;
        #pragma unroll
        for (int j = 0; j < 8; j++) nrm2 += s_red[j];

        g_xn[(size_t)i * DIM + tid] = xv * (1.0f / fmaxf(sqrtf(nrm2), 1e-8f));

        if (tid == 0) { s_cnt = 0; s_deg = 0; }
        __syncthreads();   // D: reset visible before next list build
    }
}

// ---------------------------------------------------------------------------
// Pass 2: one WARP per query. uint4 AND over padded bit-rows, decode the
// interleaved layout, then warp dot products (xn normalized -> cos==dot).
// ---------------------------------------------------------------------------
__global__ __launch_bounds__(P2_WARPS * 32) void cnp_pass2(
    const int* __restrict__ edges,   // int32 [2, Q]
    float* __restrict__ out,
    int Q)
{
    const int warp = threadIdx.x >> 5;
    const int lane = threadIdx.x & 31;
    const int q    = blockIdx.x * P2_WARPS + warp;

    __shared__ int s_list[P2_WARPS][P2_CN_CAP];
    __shared__ int s_cnt[P2_WARPS];

    if (q >= Q) return;
    if (lane == 0) s_cnt[warp] = 0;
    __syncwarp();

    const int s = edges[q];
    const int d = edges[Q + q];

    const uint4* __restrict__ bs = (const uint4*)(g_bits + (size_t)s * NW_PAD);
    const uint4* __restrict__ bd = (const uint4*)(g_bits + (size_t)d * NW_PAD);

    for (int ci = lane; ci < NW_PAD / 4; ci += 32) {
        const uint4 a = bs[ci];
        const uint4 b = bd[ci];
        uint32_t m[4] = { a.x & b.x, a.y & b.y, a.z & b.z, a.w & b.w };
        #pragma unroll
        for (int wd = 0; wd < 4; wd++) {
            uint32_t m2 = m[wd];
            const int W = (ci << 2) + wd;
            const int base = ((W >> 2) << 7) + (W & 3);
            while (m2) {
                const int bit = __ffs(m2) - 1;
                m2 &= m2 - 1;
                const int idx = atomicAdd(&s_cnt[warp], 1);
                if (idx < P2_CN_CAP) s_list[warp][idx] = base + (bit << 2);
            }
        }
    }
    __syncwarp();

    const int cn = min(s_cnt[warp], P2_CN_CAP);
    float acc = 0.0f;
    if (cn > 0) {
        float xs[8], xd[8];
        #pragma unroll
        for (int j = 0; j < 8; j++) {
            xs[j] = g_xn[(size_t)s * DIM + lane + 32*j];
            xd[j] = g_xn[(size_t)d * DIM + lane + 32*j];
        }
        for (int k = 0; k < cn; k++) {
            const int c = s_list[warp][k];
            float pl = 0.f, pr = 0.f;
            #pragma unroll
            for (int j = 0; j < 8; j++) {
                const float xc = g_xn[(size_t)c * DIM + lane + 32*j];
                pl += xs[j] * xc;
                pr += xd[j] * xc;
            }
            #pragma unroll
            for (int o = 16; o; o >>= 1) {
                pl += __shfl_xor_sync(0xffffffffu, pl, o);
                pr += __shfl_xor_sync(0xffffffffu, pr, o);
            }
            acc += pl * pr;
        }
    }

    if (lane == 0) out[q] = 1.0f / (1.0f + expf(-acc));
}

// ---------------------------------------------------------------------------
// Launch — identify inputs by element count (robust to metadata ordering).
// ---------------------------------------------------------------------------
extern "C" void kernel_launch(void* const* d_in, const int* in_sizes, int n_in,
                              void* d_out, int out_size)
{
    int i_adj = 0, i_edg = 0;
    long long best_adj = -1, best_edg = 0x7fffffffffffLL;
    for (int k = 0; k < n_in; ++k) {
        long long sz = in_sizes[k];
        if (sz > best_adj) { best_adj = sz; i_adj = k; }
        if (sz < best_edg) { best_edg = sz; i_edg = k; }
    }
    int i_emb = 0; long long best_emb = -1;
    for (int k = 0; k < n_in; ++k) {
        if (k == i_adj || k == i_edg) continue;
        if (in_sizes[k] > best_emb) { best_emb = in_sizes[k]; i_emb = k; }
    }

    const float* emb   = (const float*)d_in[i_emb];   // [N, 256] fp32
    const float* adj   = (const float*)d_in[i_adj];   // [N, N]   fp32 0/1
    const int*   edges = (const int*)d_in[i_edg];     // [2, Q]   int32
    float*       out   = (float*)d_out;               // [Q]      fp32

    const int N = in_sizes[i_emb] / DIM;  // 10000
    const int Q = in_sizes[i_edg] / 2;    // 4096

    cnp_pass1<<<GRID1, 256>>>(emb, adj, N);
    cnp_pass2<<<(Q + P2_WARPS - 1) / P2_WARPS, P2_WARPS * 32>>>(edges, out, Q);
}